// round 1
// baseline (speedup 1.0000x reference)
#include <cuda_runtime.h>
#include <math_constants.h>

#define THREADS 256
#define SEG 8192              // elements per block in passes 3/5
#define MAXB 4096
#define NELEM_MAX (1 << 24)   // problem size: 1*32*4096*128 = 2^24

// ---------------- device scratch (no allocations allowed) ----------------
__device__ unsigned int d_umin, d_umax;
__device__ int d_hist[256];
__device__ int d_blockhist[MAXB][256];
__device__ unsigned char d_qbuf[NELEM_MAX];
__device__ int d_t, d_r;
__device__ int d_tieoff[MAXB];

// order-preserving float <-> uint mapping for atomic min/max
__device__ __forceinline__ unsigned int enc_f(float f) {
    unsigned int u = __float_as_uint(f);
    return (u & 0x80000000u) ? ~u : (u | 0x80000000u);
}
__device__ __forceinline__ float dec_f(unsigned int e) {
    unsigned int u = (e & 0x80000000u) ? (e & 0x7FFFFFFFu) : ~e;
    return __uint_as_float(u);
}

// exact quantization matching jnp: ((x-min)/range)*255, round-half-even
__device__ __forceinline__ int quant(float v, float minv, float range) {
    float n = __fdiv_rn(v - minv, range);       // IEEE divide (no fast-math)
    float s = __fmul_rn(n, 255.0f);             // IEEE multiply
    int q = (int)rintf(s);                      // RNE, same as jnp.round
    return min(255, max(0, q));
}

// ---------------- pass 0: init ----------------
__global__ void k_init() {
    if (threadIdx.x == 0) { d_umin = 0xFFFFFFFFu; d_umax = 0u; }
    d_hist[threadIdx.x] = 0;
}

// ---------------- pass 1: global min/max ----------------
__global__ void k_minmax(const float* __restrict__ x, int n) {
    float lmin = CUDART_INF_F, lmax = -CUDART_INF_F;
    int n4 = n >> 2;
    const float4* x4 = reinterpret_cast<const float4*>(x);
    for (int i = blockIdx.x * blockDim.x + threadIdx.x; i < n4;
         i += gridDim.x * blockDim.x) {
        float4 v = x4[i];
        lmin = fminf(lmin, fminf(fminf(v.x, v.y), fminf(v.z, v.w)));
        lmax = fmaxf(lmax, fmaxf(fmaxf(v.x, v.y), fmaxf(v.z, v.w)));
    }
    // scalar tail (block 0 only)
    if (blockIdx.x == 0) {
        for (int i = n4 * 4 + threadIdx.x; i < n; i += blockDim.x) {
            float v = x[i];
            lmin = fminf(lmin, v);
            lmax = fmaxf(lmax, v);
        }
    }
#pragma unroll
    for (int o = 16; o; o >>= 1) {
        lmin = fminf(lmin, __shfl_xor_sync(0xFFFFFFFFu, lmin, o));
        lmax = fmaxf(lmax, __shfl_xor_sync(0xFFFFFFFFu, lmax, o));
    }
    __shared__ float smin[8], smax[8];
    int lane = threadIdx.x & 31, wid = threadIdx.x >> 5;
    if (lane == 0) { smin[wid] = lmin; smax[wid] = lmax; }
    __syncthreads();
    if (threadIdx.x == 0) {
#pragma unroll
        for (int w = 1; w < 8; w++) {
            lmin = fminf(lmin, smin[w]);
            lmax = fmaxf(lmax, smax[w]);
        }
        atomicMin(&d_umin, enc_f(lmin));
        atomicMax(&d_umax, enc_f(lmax));
    }
}

// ---------------- pass 2: quantize + per-block histogram ----------------
__global__ void k_quanthist(const float* __restrict__ x, int n) {
    __shared__ int sh[256];
    int tid = threadIdx.x;
    sh[tid] = 0;
    __syncthreads();

    float minv = dec_f(d_umin), maxv = dec_f(d_umax);
    float range = maxv - minv;
    if (range == 0.0f) range = 1.0f;

    int base = blockIdx.x * SEG;
#pragma unroll
    for (int k = 0; k < SEG; k += THREADS * 4) {
        int idx = base + k + tid * 4;
        if (idx + 3 < n) {
            float4 v = *reinterpret_cast<const float4*>(x + idx);
            int q0 = quant(v.x, minv, range);
            int q1 = quant(v.y, minv, range);
            int q2 = quant(v.z, minv, range);
            int q3 = quant(v.w, minv, range);
            atomicAdd(&sh[q0], 1);
            atomicAdd(&sh[q1], 1);
            atomicAdd(&sh[q2], 1);
            atomicAdd(&sh[q3], 1);
            uchar4 qc;
            qc.x = (unsigned char)q0; qc.y = (unsigned char)q1;
            qc.z = (unsigned char)q2; qc.w = (unsigned char)q3;
            *reinterpret_cast<uchar4*>(d_qbuf + idx) = qc;
        } else {
            for (int m = 0; m < 4; m++) {
                int j = idx + m;
                if (j < n) {
                    int q = quant(x[j], minv, range);
                    atomicAdd(&sh[q], 1);
                    d_qbuf[j] = (unsigned char)q;
                }
            }
        }
    }
    __syncthreads();
    atomicAdd(&d_hist[tid], sh[tid]);
    d_blockhist[blockIdx.x][tid] = sh[tid];
}

// ---------------- pass 3: threshold selection + tie offsets ----------------
__global__ void k_select(int nb, int keep) {
    __shared__ int sc[256];
    int tid = threadIdx.x;
    int h = d_hist[tid];

    // inclusive suffix scan: sc[v] = count(q >= v)
    sc[tid] = h;
    __syncthreads();
#pragma unroll
    for (int off = 1; off < 256; off <<= 1) {
        int add = (tid + off < 256) ? sc[tid + off] : 0;
        __syncthreads();
        sc[tid] += add;
        __syncthreads();
    }
    int ge = sc[tid];
    int gt = ge - h;
    if (gt < keep && ge >= keep) {   // exactly one bin satisfies this
        d_t = tid;
        d_r = keep - gt;             // # ties at t to keep (lowest indices)
    }
    __syncthreads();
    int t = d_t;

    // exclusive prefix scan over blocks of blockhist[b][t]
    int run = 0;
    for (int base = 0; base < nb; base += 256) {
        int idx = base + tid;
        int v = (idx < nb) ? d_blockhist[idx][t] : 0;
        sc[tid] = v;
        __syncthreads();
#pragma unroll
        for (int off = 1; off < 256; off <<= 1) {
            int add = (tid >= off) ? sc[tid - off] : 0;
            __syncthreads();
            sc[tid] += add;
            __syncthreads();
        }
        if (idx < nb) d_tieoff[idx] = run + sc[tid] - v;
        run += sc[255];
        __syncthreads();
    }
}

// ---------------- pass 4: write sparsified output ----------------
__global__ void k_output(float* __restrict__ out, int n, long long out_n) {
    int tid = threadIdx.x;
    int lane = tid & 31, wid = tid >> 5;
    int t = d_t, r = d_r;

    __shared__ int s_warp[8];
    __shared__ int s_base;
    if (tid == 0) s_base = d_tieoff[blockIdx.x];
    __syncthreads();

    int base = blockIdx.x * SEG;
#pragma unroll
    for (int k = 0; k < SEG; k += THREADS * 4) {
        int idx = base + k + tid * 4;
        int q0 = -1, q1 = -1, q2 = -1, q3 = -1;
        bool full = (idx + 3 < n);
        if (full) {
            uchar4 qc = *reinterpret_cast<const uchar4*>(d_qbuf + idx);
            q0 = qc.x; q1 = qc.y; q2 = qc.z; q3 = qc.w;
        } else {
            if (idx + 0 < n) q0 = d_qbuf[idx + 0];
            if (idx + 1 < n) q1 = d_qbuf[idx + 1];
            if (idx + 2 < n) q2 = d_qbuf[idx + 2];
            if (idx + 3 < n) q3 = d_qbuf[idx + 3];
        }
        int cnt = (q0 == t) + (q1 == t) + (q2 == t) + (q3 == t);

        // block-wide exclusive scan of tie counts (index order == tid order)
        int x = cnt;
#pragma unroll
        for (int o = 1; o < 32; o <<= 1) {
            int y = __shfl_up_sync(0xFFFFFFFFu, x, o);
            if (lane >= o) x += y;
        }
        if (lane == 31) s_warp[wid] = x;
        __syncthreads();
        if (tid < 8) {
            int w = s_warp[tid];
#pragma unroll
            for (int o = 1; o < 8; o <<= 1) {
                int y = __shfl_up_sync(0xFFu, w, o);
                if (tid >= o) w += y;
            }
            s_warp[tid] = w;   // inclusive warp totals
        }
        __syncthreads();
        int excl  = x - cnt + (wid ? s_warp[wid - 1] : 0);
        int total = s_warp[7];
        int rank  = s_base + excl;

        float o0, o1, o2, o3;
        if (q0 > t) o0 = (float)q0; else if (q0 == t) { o0 = (rank < r) ? (float)q0 : 0.0f; rank++; } else o0 = 0.0f;
        if (q1 > t) o1 = (float)q1; else if (q1 == t) { o1 = (rank < r) ? (float)q1 : 0.0f; rank++; } else o1 = 0.0f;
        if (q2 > t) o2 = (float)q2; else if (q2 == t) { o2 = (rank < r) ? (float)q2 : 0.0f; rank++; } else o2 = 0.0f;
        if (q3 > t) o3 = (float)q3; else if (q3 == t) { o3 = (rank < r) ? (float)q3 : 0.0f; rank++; } else o3 = 0.0f;

        if (full) {
            float4 ov; ov.x = o0; ov.y = o1; ov.z = o2; ov.w = o3;
            *reinterpret_cast<float4*>(out + idx) = ov;
        } else {
            if (idx + 0 < n) out[idx + 0] = o0;
            if (idx + 1 < n) out[idx + 1] = o1;
            if (idx + 2 < n) out[idx + 2] = o2;
        }
        __syncthreads();
        if (tid == 0) s_base += total;
        __syncthreads();
    }

    if (blockIdx.x == 0 && tid == 0 && out_n >= (long long)n + 3) {
        float minv = dec_f(d_umin), maxv = dec_f(d_umax);
        float range = maxv - minv;
        if (range == 0.0f) range = 1.0f;
        out[n + 0] = minv;
        out[n + 1] = maxv;
        out[n + 2] = range;
    }
}

// ---------------- launch ----------------
extern "C" void kernel_launch(void* const* d_in, const int* in_sizes, int n_in,
                              void* d_out, int out_size) {
    const float* x = (const float*)d_in[0];
    float* out = (float*)d_out;
    int n = in_sizes[0];
    int nb = (n + SEG - 1) / SEG;            // 2048 for 2^24
    int keep = (int)((double)n * 0.5);       // int(total * (1 - SPARSE_RATIO))

    k_init<<<1, 256>>>();
    k_minmax<<<2048, THREADS>>>(x, n);
    k_quanthist<<<nb, THREADS>>>(x, n);
    k_select<<<1, 256>>>(nb, keep);
    k_output<<<nb, THREADS>>>(out, n, (long long)out_size);
}

// round 2
// speedup vs baseline: 1.1329x; 1.1329x over previous
#include <cuda_runtime.h>
#include <math_constants.h>

#define THREADS 256
#define SEG 8192              // elements per block in quant/output passes
#define MAXB 4096
#define NELEM_MAX (1 << 24)   // 1*32*4096*128 = 2^24

// ---------------- device scratch (no allocations allowed) ----------------
__device__ unsigned int d_umin = 0xFFFFFFFFu;   // re-armed at end of k_output
__device__ unsigned int d_umax = 0u;
__device__ int d_hist[256];                     // zeroed at end of k_select
__device__ int d_bhT[256][MAXB];                // bin-major per-block histogram
__device__ unsigned char d_qbuf[NELEM_MAX];
__device__ int d_t, d_r;
__device__ int d_tieoff[MAXB];

// order-preserving float <-> uint mapping for atomic min/max
__device__ __forceinline__ unsigned int enc_f(float f) {
    unsigned int u = __float_as_uint(f);
    return (u & 0x80000000u) ? ~u : (u | 0x80000000u);
}
__device__ __forceinline__ float dec_f(unsigned int e) {
    unsigned int u = (e & 0x80000000u) ? (e & 0x7FFFFFFFu) : ~e;
    return __uint_as_float(u);
}

// exact quantization matching jnp: ((x-min)/range)*255, round-half-even
__device__ __forceinline__ int quant(float v, float minv, float range) {
    float n = __fdiv_rn(v - minv, range);       // IEEE divide (no fast-math)
    float s = __fmul_rn(n, 255.0f);             // IEEE multiply
    int q = (int)rintf(s);                      // RNE, same as jnp.round
    return min(255, max(0, q));
}

// ---------------- pass 1: global min/max ----------------
__global__ void k_minmax(const float* __restrict__ x, int n) {
    float lmin = CUDART_INF_F, lmax = -CUDART_INF_F;
    int n4 = n >> 2;
    const float4* x4 = reinterpret_cast<const float4*>(x);
    for (int i = blockIdx.x * blockDim.x + threadIdx.x; i < n4;
         i += gridDim.x * blockDim.x) {
        float4 v = x4[i];
        lmin = fminf(lmin, fminf(fminf(v.x, v.y), fminf(v.z, v.w)));
        lmax = fmaxf(lmax, fmaxf(fmaxf(v.x, v.y), fmaxf(v.z, v.w)));
    }
    if (blockIdx.x == 0) {  // scalar tail
        for (int i = n4 * 4 + threadIdx.x; i < n; i += blockDim.x) {
            float v = x[i];
            lmin = fminf(lmin, v);
            lmax = fmaxf(lmax, v);
        }
    }
#pragma unroll
    for (int o = 16; o; o >>= 1) {
        lmin = fminf(lmin, __shfl_xor_sync(0xFFFFFFFFu, lmin, o));
        lmax = fmaxf(lmax, __shfl_xor_sync(0xFFFFFFFFu, lmax, o));
    }
    __shared__ float smin[8], smax[8];
    int lane = threadIdx.x & 31, wid = threadIdx.x >> 5;
    if (lane == 0) { smin[wid] = lmin; smax[wid] = lmax; }
    __syncthreads();
    if (threadIdx.x == 0) {
#pragma unroll
        for (int w = 1; w < 8; w++) {
            lmin = fminf(lmin, smin[w]);
            lmax = fmaxf(lmax, smax[w]);
        }
        atomicMin(&d_umin, enc_f(lmin));
        atomicMax(&d_umax, enc_f(lmax));
    }
}

// ---------------- pass 2: quantize + per-block histogram ----------------
__global__ void k_quanthist(const float* __restrict__ x, int n) {
    __shared__ int sh[8][256];   // per-warp sub-histograms (8 KB)
    int tid = threadIdx.x;
    int wid = tid >> 5;
#pragma unroll
    for (int i = tid; i < 8 * 256; i += THREADS) ((int*)sh)[i] = 0;
    __syncthreads();

    float minv = dec_f(d_umin), maxv = dec_f(d_umax);
    float range = maxv - minv;
    if (range == 0.0f) range = 1.0f;

    int base = blockIdx.x * SEG;
#pragma unroll
    for (int k = 0; k < SEG; k += THREADS * 4) {
        int idx = base + k + tid * 4;
        if (idx + 3 < n) {
            float4 v = *reinterpret_cast<const float4*>(x + idx);
            int q0 = quant(v.x, minv, range);
            int q1 = quant(v.y, minv, range);
            int q2 = quant(v.z, minv, range);
            int q3 = quant(v.w, minv, range);
            atomicAdd(&sh[wid][q0], 1);
            atomicAdd(&sh[wid][q1], 1);
            atomicAdd(&sh[wid][q2], 1);
            atomicAdd(&sh[wid][q3], 1);
            uchar4 qc;
            qc.x = (unsigned char)q0; qc.y = (unsigned char)q1;
            qc.z = (unsigned char)q2; qc.w = (unsigned char)q3;
            *reinterpret_cast<uchar4*>(d_qbuf + idx) = qc;
        } else {
            for (int m = 0; m < 4; m++) {
                int j = idx + m;
                if (j < n) {
                    int q = quant(x[j], minv, range);
                    atomicAdd(&sh[wid][q], 1);
                    d_qbuf[j] = (unsigned char)q;
                }
            }
        }
    }
    __syncthreads();
    int tot = 0;
#pragma unroll
    for (int w = 0; w < 8; w++) tot += sh[w][tid];
    atomicAdd(&d_hist[tid], tot);
    d_bhT[tid][blockIdx.x] = tot;     // bin-major: column t is contiguous
}

// ---------------- pass 3: threshold + tie-offset scan (1024 threads) -------
__global__ void k_select(int nb, int keep) {
    __shared__ int sc[256];
    __shared__ int s_t;
    __shared__ int wsum[32];
    int tid = threadIdx.x;
    int lane = tid & 31, wid = tid >> 5;

    // -- phase A: suffix scan over 256 bins (threads 0..255 active) --
    int h = 0;
    if (tid < 256) { h = d_hist[tid]; sc[tid] = h; }
    __syncthreads();
#pragma unroll
    for (int off = 1; off < 256; off <<= 1) {
        int add = 0;
        if (tid < 256 && tid + off < 256) add = sc[tid + off];
        __syncthreads();
        if (tid < 256) sc[tid] += add;
        __syncthreads();
    }
    if (tid < 256) {
        int ge = sc[tid];
        int gt = ge - h;
        if (gt < keep && ge >= keep) {   // exactly one bin satisfies this
            d_t = tid;
            d_r = keep - gt;
            s_t = tid;
        }
        d_hist[tid] = 0;                 // re-arm for next run
    }
    __syncthreads();
    int t = s_t;

    // -- phase B: exclusive prefix scan of d_bhT[t][0..nb) (contiguous) --
    const int* col = d_bhT[t];
    int i0 = 2 * tid, i1 = 2 * tid + 1;
    int a = (i0 < nb) ? col[i0] : 0;
    int b = (i1 < nb) ? col[i1] : 0;
    int s = a + b;
    int x = s;
#pragma unroll
    for (int o = 1; o < 32; o <<= 1) {
        int y = __shfl_up_sync(0xFFFFFFFFu, x, o);
        if (lane >= o) x += y;
    }
    if (lane == 31) wsum[wid] = x;
    __syncthreads();
    if (tid < 32) {
        int w = wsum[tid];
#pragma unroll
        for (int o = 1; o < 32; o <<= 1) {
            int y = __shfl_up_sync(0xFFFFFFFFu, w, o);
            if (tid >= o) w += y;
        }
        wsum[tid] = w;
    }
    __syncthreads();
    int incl = x + (wid ? wsum[wid - 1] : 0);
    int excl = incl - s;
    if (i0 < nb) d_tieoff[i0] = excl;
    if (i1 < nb) d_tieoff[i1] = excl + a;
}

// ---------------- pass 4: write sparsified output ----------------
__global__ void k_output(float* __restrict__ out, int n, long long out_n) {
    int tid = threadIdx.x;
    int lane = tid & 31, wid = tid >> 5;
    int t = d_t, r = d_r;

    __shared__ int s_warp[8];
    __shared__ int s_base;
    if (tid == 0) s_base = d_tieoff[blockIdx.x];
    __syncthreads();

    int base = blockIdx.x * SEG;
#pragma unroll
    for (int k = 0; k < SEG; k += THREADS * 4) {
        int idx = base + k + tid * 4;
        int q0 = -1, q1 = -1, q2 = -1, q3 = -1;
        bool full = (idx + 3 < n);
        if (full) {
            uchar4 qc = *reinterpret_cast<const uchar4*>(d_qbuf + idx);
            q0 = qc.x; q1 = qc.y; q2 = qc.z; q3 = qc.w;
        } else {
            if (idx + 0 < n) q0 = d_qbuf[idx + 0];
            if (idx + 1 < n) q1 = d_qbuf[idx + 1];
            if (idx + 2 < n) q2 = d_qbuf[idx + 2];
            if (idx + 3 < n) q3 = d_qbuf[idx + 3];
        }
        int cnt = (q0 == t) + (q1 == t) + (q2 == t) + (q3 == t);

        // block-wide exclusive scan of tie counts (index order == tid order)
        int x = cnt;
#pragma unroll
        for (int o = 1; o < 32; o <<= 1) {
            int y = __shfl_up_sync(0xFFFFFFFFu, x, o);
            if (lane >= o) x += y;
        }
        if (lane == 31) s_warp[wid] = x;
        __syncthreads();
        if (tid < 8) {
            int w = s_warp[tid];
#pragma unroll
            for (int o = 1; o < 8; o <<= 1) {
                int y = __shfl_up_sync(0xFFu, w, o);
                if (tid >= o) w += y;
            }
            s_warp[tid] = w;   // inclusive warp totals
        }
        __syncthreads();
        int excl  = x - cnt + (wid ? s_warp[wid - 1] : 0);
        int total = s_warp[7];
        int rank  = s_base + excl;

        float o0, o1, o2, o3;
        if (q0 > t) o0 = (float)q0; else if (q0 == t) { o0 = (rank < r) ? (float)q0 : 0.0f; rank++; } else o0 = 0.0f;
        if (q1 > t) o1 = (float)q1; else if (q1 == t) { o1 = (rank < r) ? (float)q1 : 0.0f; rank++; } else o1 = 0.0f;
        if (q2 > t) o2 = (float)q2; else if (q2 == t) { o2 = (rank < r) ? (float)q2 : 0.0f; rank++; } else o2 = 0.0f;
        if (q3 > t) o3 = (float)q3; else if (q3 == t) { o3 = (rank < r) ? (float)q3 : 0.0f; rank++; } else o3 = 0.0f;

        if (full) {
            float4 ov; ov.x = o0; ov.y = o1; ov.z = o2; ov.w = o3;
            *reinterpret_cast<float4*>(out + idx) = ov;
        } else {
            if (idx + 0 < n) out[idx + 0] = o0;
            if (idx + 1 < n) out[idx + 1] = o1;
            if (idx + 2 < n) out[idx + 2] = o2;
        }
        __syncthreads();
        if (tid == 0) s_base += total;
        __syncthreads();
    }

    if (blockIdx.x == 0 && tid == 0) {
        float minv = dec_f(d_umin), maxv = dec_f(d_umax);
        float range = maxv - minv;
        if (range == 0.0f) range = 1.0f;
        if (out_n >= (long long)n + 3) {
            out[n + 0] = minv;
            out[n + 1] = maxv;
            out[n + 2] = range;
        }
        // re-arm min/max for the next graph replay
        d_umin = 0xFFFFFFFFu;
        d_umax = 0u;
    }
}

// ---------------- launch ----------------
extern "C" void kernel_launch(void* const* d_in, const int* in_sizes, int n_in,
                              void* d_out, int out_size) {
    const float* x = (const float*)d_in[0];
    float* out = (float*)d_out;
    int n = in_sizes[0];
    int nb = (n + SEG - 1) / SEG;            // 2048 for 2^24
    int keep = (int)((double)n * 0.5);       // int(total * (1 - SPARSE_RATIO))

    k_minmax<<<2048, THREADS>>>(x, n);
    k_quanthist<<<nb, THREADS>>>(x, n);
    k_select<<<1, 1024>>>(nb, keep);
    k_output<<<nb, THREADS>>>(out, n, (long long)out_size);
}